// round 9
// baseline (speedup 1.0000x reference)
#include <cuda_runtime.h>

#define TM        8
#define NTHREADS  128
#define M_DIM     8192
#define N_DIM     8192

typedef unsigned long long u64;

// ---- packed f32x2 helpers (sm_103a) ----
__device__ __forceinline__ u64 pack2(float a, float b) {
    u64 r;
    asm("mov.b64 %0, {%1, %2};" : "=l"(r) : "f"(a), "f"(b));
    return r;
}
__device__ __forceinline__ u64 fma2(u64 a, u64 b, u64 c) {
    u64 d;
    asm("fma.rn.f32x2 %0, %1, %2, %3;" : "=l"(d) : "l"(a), "l"(b), "l"(c));
    return d;
}
__device__ __forceinline__ void unpack2(u64 v, float& a, float& b) {
    asm("mov.b64 {%0, %1}, %2;" : "=f"(a), "=f"(b) : "l"(v));
}

// y[r][m] = sum_n code[nib(m,n)] * absmax[(m*N+n)/64] * x[r][n] + bias[m]
// qweight int32 = one packed byte: hi nibble = even col, lo nibble = odd col.
//
// TM=8 rows of W per block amortizes x L1 traffic (the R5 bottleneck) over
// twice the rows. Register fit achieved by collapsing (even,odd) f32x2 sums
// to scalar f32 accumulators per chunk (acc: 32 f32 instead of 32 u64).
__global__ void __launch_bounds__(NTHREADS, 5)
fp4_gemv_kernel(const float* __restrict__ x,
                const int*   __restrict__ qweight,
                const float* __restrict__ absmax,
                const float* __restrict__ code,
                const float* __restrict__ bias,
                float*       __restrict__ out)
{
    __shared__ float code_sh[16];          // 16 floats = 16 banks: conflict-free
    __shared__ float red[4][TM * 4];

    const int tid = threadIdx.x;
    const int w   = tid >> 5;
    const int l   = tid & 31;

    if (tid < 16) code_sh[tid] = code[tid];
    __syncthreads();

    const int m0 = blockIdx.x * TM;
    const int4* __restrict__ qw4 = (const int4*)qweight;

    float acc[TM][4];                      // [w-row][x-row], scalar f32
    #pragma unroll
    for (int mi = 0; mi < TM; ++mi)
        #pragma unroll
        for (int r = 0; r < 4; ++r) acc[mi][r] = 0.0f;

    const int lane_col = w * 32 + l;       // col4 base within each chunk of 128

    #pragma unroll 2
    for (int c = 0; c < 8; ++c) {
        const int col4 = c * 128 + lane_col;   // int4 index in row [0,1024)
        const int n0   = col4 * 8;             // first weight column
        const int amc  = col4 >> 3;            // absmax block within row

        // x pairs: xp[j][r] = (x[r][n0+2j], x[r][n0+2j+1]) — fma2-ready, no packs
        u64 xp[4][4];
        #pragma unroll
        for (int r = 0; r < 4; ++r) {
            ulonglong2 a = __ldg((const ulonglong2*)(x + r * N_DIM + n0));
            ulonglong2 b = __ldg((const ulonglong2*)(x + r * N_DIM + n0 + 4));
            xp[0][r] = a.x; xp[1][r] = a.y;
            xp[2][r] = b.x; xp[3][r] = b.y;
        }

        #pragma unroll
        for (int g = 0; g < 2; ++g) {          // two groups of 4 W-rows
            int4  q[4];
            float am[4];
            #pragma unroll
            for (int mi = 0; mi < 4; ++mi) {
                const int m = m0 + g * 4 + mi;
                q[mi]  = __ldg(&qw4[m * 1024 + col4]);
                am[mi] = __ldg(&absmax[m * 128 + amc]);
            }

            #pragma unroll
            for (int mi = 0; mi < 4; ++mi) {
                const unsigned bb[4] = { (unsigned)q[mi].x, (unsigned)q[mi].y,
                                         (unsigned)q[mi].z, (unsigned)q[mi].w };
                u64 t[4] = {0ULL, 0ULL, 0ULL, 0ULL};   // per x-row (even,odd) sums
                #pragma unroll
                for (int j = 0; j < 4; ++j) {
                    const unsigned b = bb[j];                    // 0..255
                    const u64 c2 = pack2(code_sh[b >> 4], code_sh[b & 15]);
                    t[0] = fma2(c2, xp[j][0], t[0]);
                    t[1] = fma2(c2, xp[j][1], t[1]);
                    t[2] = fma2(c2, xp[j][2], t[2]);
                    t[3] = fma2(c2, xp[j][3], t[3]);
                }
                const int ai = g * 4 + mi;
                #pragma unroll
                for (int r = 0; r < 4; ++r) {
                    float e, o;
                    unpack2(t[r], e, o);               // free: register halves
                    acc[ai][r] = fmaf(e + o, am[mi], acc[ai][r]);
                }
            }
        }
    }

    // ---- reduction: warp shfl, then cross-warp via smem ----
    float vals[TM * 4];
    #pragma unroll
    for (int mi = 0; mi < TM; ++mi)
        #pragma unroll
        for (int r = 0; r < 4; ++r) vals[mi * 4 + r] = acc[mi][r];

    #pragma unroll
    for (int i = 0; i < TM * 4; ++i) {
        float v = vals[i];
        v += __shfl_xor_sync(0xffffffffu, v, 16);
        v += __shfl_xor_sync(0xffffffffu, v, 8);
        v += __shfl_xor_sync(0xffffffffu, v, 4);
        v += __shfl_xor_sync(0xffffffffu, v, 2);
        v += __shfl_xor_sync(0xffffffffu, v, 1);
        vals[i] = v;
    }
    if (l == 0) {
        #pragma unroll
        for (int i = 0; i < TM * 4; ++i) red[w][i] = vals[i];
    }
    __syncthreads();

    if (tid < TM * 4) {
        float s = red[0][tid] + red[1][tid] + red[2][tid] + red[3][tid];
        const int mi = tid >> 2;
        const int r  = tid & 3;
        out[r * M_DIM + m0 + mi] = s + bias[m0 + mi];
    }
}

extern "C" void kernel_launch(void* const* d_in, const int* in_sizes, int n_in,
                              void* d_out, int out_size)
{
    const float* x       = (const float*)d_in[0];
    const int*   qweight = (const int*)  d_in[1];
    const float* absmax  = (const float*)d_in[2];
    const float* code    = (const float*)d_in[3];
    const float* bias    = (const float*)d_in[4];
    float*       out     = (float*)d_out;

    fp4_gemv_kernel<<<M_DIM / TM, NTHREADS>>>(x, qweight, absmax, code, bias, out);
}

// round 10
// speedup vs baseline: 1.8543x; 1.8543x over previous
#include <cuda_runtime.h>

#define TM        4
#define NTHREADS  128
#define M_DIM     8192
#define N_DIM     8192

typedef unsigned long long u64;

// ---- packed f32x2 helpers (sm_103a) ----
__device__ __forceinline__ u64 pack2(float a, float b) {
    u64 r;
    asm("mov.b64 %0, {%1, %2};" : "=l"(r) : "f"(a), "f"(b));
    return r;
}
__device__ __forceinline__ u64 fma2(u64 a, u64 b, u64 c) {
    u64 d;
    asm("fma.rn.f32x2 %0, %1, %2, %3;" : "=l"(d) : "l"(a), "l"(b), "l"(c));
    return d;
}
__device__ __forceinline__ void unpack2(u64 v, float& a, float& b) {
    asm("mov.b64 {%0, %1}, %2;" : "=f"(a), "=f"(b) : "l"(v));
}

// y[r][m] = sum_n code[nib(m,n)] * absmax[(m*N+n)/64] * x[r][n] + bias[m]
// qweight int32 = one packed byte: hi nibble = even col, lo nibble = odd col.
//
// R6 structure (best so far) + BANK-REPLICATED codebook: 32 lane-striped
// copies of the 16-entry table so every lookup reads its own bank ->
// guaranteed 1 wavefront per LDS regardless of nibble distribution.
__global__ void __launch_bounds__(NTHREADS, 4)
fp4_gemv_kernel(const float* __restrict__ x,
                const int*   __restrict__ qweight,
                const float* __restrict__ absmax,
                const float* __restrict__ code,
                const float* __restrict__ bias,
                float*       __restrict__ out)
{
    __shared__ float code_rep[16 * 32];    // [idx][lane]: bank == lane, conflict-free
    __shared__ float red[4][TM * 4];

    const int tid = threadIdx.x;
    const int w   = tid >> 5;
    const int l   = tid & 31;

    #pragma unroll
    for (int i = tid; i < 16 * 32; i += NTHREADS)
        code_rep[i] = code[i >> 5];
    __syncthreads();

    const float* __restrict__ my_tab = code_rep + l;   // this lane's bank column

    const int m0 = blockIdx.x * TM;
    const int4* __restrict__ qw4 = (const int4*)qweight;

    u64 acc[TM][4];                        // [w-row][x-row] = (even,odd) sums
    #pragma unroll
    for (int mi = 0; mi < TM; ++mi)
        #pragma unroll
        for (int r = 0; r < 4; ++r) acc[mi][r] = 0ULL;

    const int lane_col = w * 32 + l;       // col4 base within each chunk of 128

    #pragma unroll 2
    for (int c = 0; c < 8; ++c) {
        const int col4 = c * 128 + lane_col;   // int4 index in row [0,1024)
        const int n0   = col4 * 8;             // first weight column

        // ---- batch all global loads up front (max MLP) ----
        int4  q[TM];
        float am[TM];
        #pragma unroll
        for (int mi = 0; mi < TM; ++mi) {
            q[mi]  = __ldg(&qw4[(m0 + mi) * 1024 + col4]);
            am[mi] = __ldg(&absmax[(m0 + mi) * 128 + (col4 >> 3)]);
        }

        // x pairs: xp[j][r] = (x[r][n0+2j], x[r][n0+2j+1]) — fma2-ready
        u64 xp[4][4];
        #pragma unroll
        for (int r = 0; r < 4; ++r) {
            ulonglong2 a = __ldg((const ulonglong2*)(x + r * N_DIM + n0));
            ulonglong2 b = __ldg((const ulonglong2*)(x + r * N_DIM + n0 + 4));
            xp[0][r] = a.x; xp[1][r] = a.y;
            xp[2][r] = b.x; xp[3][r] = b.y;
        }

        // ---- decode + accumulate ----
        #pragma unroll
        for (int mi = 0; mi < TM; ++mi) {
            const unsigned bb[4] = { (unsigned)q[mi].x, (unsigned)q[mi].y,
                                     (unsigned)q[mi].z, (unsigned)q[mi].w };
            u64 t[4] = {0ULL, 0ULL, 0ULL, 0ULL};   // per x-row, unscaled
            #pragma unroll
            for (int j = 0; j < 4; ++j) {
                const unsigned b = bb[j];                    // 0..255
                // replicated table: hi idx -> (b&0xF0)*2 floats, lo -> (b&15)*32
                const float chi = my_tab[(b & 0xF0u) << 1];
                const float clo = my_tab[(b & 0x0Fu) << 5];
                const u64 c2 = pack2(chi, clo);
                t[0] = fma2(c2, xp[j][0], t[0]);
                t[1] = fma2(c2, xp[j][1], t[1]);
                t[2] = fma2(c2, xp[j][2], t[2]);
                t[3] = fma2(c2, xp[j][3], t[3]);
            }
            const u64 am2 = pack2(am[mi], am[mi]);
            #pragma unroll
            for (int r = 0; r < 4; ++r)
                acc[mi][r] = fma2(t[r], am2, acc[mi][r]);
        }
    }

    // ---- epilogue: halves sum (free unpack), shfl reduce, cross-warp ----
    float vals[TM * 4];
    #pragma unroll
    for (int mi = 0; mi < TM; ++mi)
        #pragma unroll
        for (int r = 0; r < 4; ++r) {
            float e, o;
            unpack2(acc[mi][r], e, o);
            vals[mi * 4 + r] = e + o;
        }
    #pragma unroll
    for (int i = 0; i < TM * 4; ++i) {
        float v = vals[i];
        v += __shfl_xor_sync(0xffffffffu, v, 16);
        v += __shfl_xor_sync(0xffffffffu, v, 8);
        v += __shfl_xor_sync(0xffffffffu, v, 4);
        v += __shfl_xor_sync(0xffffffffu, v, 2);
        v += __shfl_xor_sync(0xffffffffu, v, 1);
        vals[i] = v;
    }
    if (l == 0) {
        #pragma unroll
        for (int i = 0; i < TM * 4; ++i) red[w][i] = vals[i];
    }
    __syncthreads();

    if (tid < TM * 4) {
        float s = red[0][tid] + red[1][tid] + red[2][tid] + red[3][tid];
        const int mi = tid >> 2;
        const int r  = tid & 3;
        out[r * M_DIM + m0 + mi] = s + bias[m0 + mi];
    }
}

extern "C" void kernel_launch(void* const* d_in, const int* in_sizes, int n_in,
                              void* d_out, int out_size)
{
    const float* x       = (const float*)d_in[0];
    const int*   qweight = (const int*)  d_in[1];
    const float* absmax  = (const float*)d_in[2];
    const float* code    = (const float*)d_in[3];
    const float* bias    = (const float*)d_in[4];
    float*       out     = (float*)d_out;

    fp4_gemv_kernel<<<M_DIM / TM, NTHREADS>>>(x, qweight, absmax, code, bias, out);
}